// round 12
// baseline (speedup 1.0000x reference)
#include <cuda_runtime.h>
#include <cuda_bf16.h>
#include <stdint.h>
#include <math.h>

#define NN_ 8192
#define FF_ 512
#define HH_ 256
#define RR_ 16
#define BB_ 32
#define LL_ 256
#define CC_ 7
#define EE_ 262144
#define NBASE_ 30
#define DD_ 768
#define RH_ 4096
#define NBIN (NN_ * RR_)

typedef __nv_bfloat16 bf16;

// ---------------- scratch ----------------
__device__ __align__(16) float g_xw[(size_t)NN_ * RH_];
__device__ int   g_cnt[NBIN];
__device__ __align__(16) float g_cat[NN_ * FF_];      // [:,0:256]=agg2 [:,256:512]=out1
__device__ __align__(16) float g_scores[BB_ * LL_ * LL_];
__device__ __align__(16) float g_hidden[NN_ * HH_];
__device__ __align__(16) float g_logits[NN_ * CC_];

__device__ __align__(16) bf16 g_xh[NN_*FF_],   g_xl[NN_*FF_];
__device__ __align__(16) bf16 g_wth[RH_*FF_],  g_wtl[RH_*FF_];
__device__ __align__(16) bf16 g_r1th[HH_*FF_], g_r1tl[HH_*FF_];
__device__ __align__(16) bf16 g_w2th[HH_*FF_], g_w2tl[HH_*FF_];
__device__ __align__(16) bf16 g_wath[DD_*DD_], g_watl[DD_*DD_];
__device__ __align__(16) bf16 g_wlth[HH_*DD_], g_wltl[HH_*DD_];
__device__ __align__(16) bf16 g_cath[NN_*FF_], g_catl[NN_*FF_];
__device__ __align__(16) bf16 g_emoh[NN_*DD_], g_emol[NN_*DD_];
__device__ __align__(16) bf16 g_Xh[NN_*DD_],   g_Xl[NN_*DD_];
__device__ __align__(16) bf16 g_ah[BB_*LL_*LL_], g_al[BB_*LL_*LL_];
__device__ __align__(16) bf16 g_eTh[BB_*DD_*LL_], g_eTl[BB_*DD_*LL_];
__device__ __align__(16) bf16 g_atth[NN_*DD_], g_attl[NN_*DD_];

// ---------------- helpers ----------------
__device__ __forceinline__ uint32_t smem_u32(const void* p) {
    uint32_t a;
    asm("{ .reg .u64 t; cvta.to.shared.u64 t, %1; cvt.u32.u64 %0, t; }" : "=r"(a) : "l"(p));
    return a;
}
__device__ __forceinline__ void cpasync16(uint32_t dst, const void* src) {
    asm volatile("cp.async.cg.shared.global [%0], [%1], 16;" :: "r"(dst), "l"(src));
}
__device__ __forceinline__ void ldsm4(uint32_t* r, uint32_t addr) {
    asm volatile("ldmatrix.sync.aligned.m8n8.x4.shared.b16 {%0,%1,%2,%3}, [%4];"
        : "=r"(r[0]), "=r"(r[1]), "=r"(r[2]), "=r"(r[3]) : "r"(addr));
}
__device__ __forceinline__ void mma16816(float* c, const uint32_t* a, const uint32_t* b) {
    asm volatile("mma.sync.aligned.m16n8k16.row.col.f32.bf16.bf16.f32 "
        "{%0,%1,%2,%3},{%4,%5,%6,%7},{%8,%9},{%0,%1,%2,%3};"
        : "+f"(c[0]), "+f"(c[1]), "+f"(c[2]), "+f"(c[3])
        : "r"(a[0]), "r"(a[1]), "r"(a[2]), "r"(a[3]), "r"(b[0]), "r"(b[1]));
}
__device__ __forceinline__ void red4(float* p, float4 v) {
    asm volatile("red.global.add.v4.f32 [%0], {%1,%2,%3,%4};"
        :: "l"(p), "f"(v.x), "f"(v.y), "f"(v.z), "f"(v.w) : "memory");
}

// ---------------- HMMA GEMM: C[128x256/CTA] = (Ah+Al) @ (Bh+Bl)^T ----------------
// A [M,K] row-major bf16 split, B [N,K] row-major bf16 split. K%32==0, M%128==0, N%256==0.
// 8 warps as 2(M) x 4(N); warp tile 64x64.
#define TSTRIDE 80
#define TILE_A  10240            // 128 rows * 80
#define TILE_BN 20480            // 256 rows * 80
#define OFF_AL  10240
#define OFF_BH  20480
#define OFF_BL  40960
#define STAGE_B 61440
#define SMEM_BYTES (2 * STAGE_B)

template <int EPI, int HASB, int OSPL>
__global__ void __launch_bounds__(256, 1) mmagemm_k(
    const bf16* __restrict__ Ah, const bf16* __restrict__ Al,
    const bf16* __restrict__ Bh, const bf16* __restrict__ Bl,
    float* __restrict__ C, bf16* __restrict__ Oh, bf16* __restrict__ Ol,
    const float* __restrict__ bias,
    int K, int ldc, long long sA, long long sB, long long sC)
{
    extern __shared__ __align__(16) char smem[];
    const int tid = threadIdx.x, lane = tid & 31, wid = tid >> 5;
    const int wm = (wid >> 2) * 64, wn = (wid & 3) * 64;
    const int bm = blockIdx.y << 7, bn = blockIdx.x << 8;
    Ah += blockIdx.z * sA;  Al += blockIdx.z * sA;
    Bh += blockIdx.z * sB;  Bl += blockIdx.z * sB;
    const uint32_t sbase = smem_u32(smem);
    const size_t rsk = (size_t)K * 2;

    float acc[4][8][4];
#pragma unroll
    for (int i = 0; i < 4; i++)
#pragma unroll
        for (int j = 0; j < 8; j++)
#pragma unroll
            for (int r = 0; r < 4; r++) acc[i][j][r] = 0.f;

    const char* pA0 = (const char*)Ah + (size_t)bm * rsk;
    const char* pA1 = (const char*)Al + (size_t)bm * rsk;
    const char* pB0 = (const char*)Bh + (size_t)bn * rsk;
    const char* pB1 = (const char*)Bl + (size_t)bn * rsk;

    auto issue = [&](int stage, int k0) {
        uint32_t d0 = sbase + stage * STAGE_B;
        size_t kb = (size_t)k0 * 2;
        // A: 128 rows x 64B (hi, lo) = 512 chunk-tasks
#pragma unroll
        for (int i = 0; i < 2; i++) {
            int task = tid + i * 256;
            int row = task >> 2, ch = task & 3;
            uint32_t doff = row * TSTRIDE + ch * 16;
            size_t goff = (size_t)row * rsk + kb + ch * 16;
            cpasync16(d0 + doff,          pA0 + goff);
            cpasync16(d0 + OFF_AL + doff, pA1 + goff);
        }
        // B: 256 rows x 64B (hi, lo) = 1024 chunk-tasks
#pragma unroll
        for (int i = 0; i < 4; i++) {
            int task = tid + i * 256;
            int row = task >> 2, ch = task & 3;
            uint32_t doff = row * TSTRIDE + ch * 16;
            size_t goff = (size_t)row * rsk + kb + ch * 16;
            cpasync16(d0 + OFF_BH + doff, pB0 + goff);
            cpasync16(d0 + OFF_BL + doff, pB1 + goff);
        }
        asm volatile("cp.async.commit_group;" ::: "memory");
    };

    const int NK = K >> 5;
    issue(0, 0);
#pragma unroll 1
    for (int k = 0; k < NK; k++) {
        const int st = k & 1;
        if (k + 1 < NK) {
            issue(st ^ 1, (k + 1) << 5);
            asm volatile("cp.async.wait_group 1;" ::: "memory");
        } else {
            asm volatile("cp.async.wait_group 0;" ::: "memory");
        }
        __syncthreads();
        const uint32_t aB = sbase + st * STAGE_B;
        const int idx8 = lane & 7, q = lane >> 3;
#pragma unroll
        for (int ks = 0; ks < 2; ks++) {
            uint32_t arh[4][4], arl[4][4];
#pragma unroll
            for (int mf = 0; mf < 4; mf++) {
                uint32_t byte = (uint32_t)(wm + mf * 16 + (q & 1) * 8 + idx8) * TSTRIDE
                              + ks * 32 + (q >> 1) * 16;
                ldsm4(arh[mf], aB + byte);
                ldsm4(arl[mf], aB + OFF_AL + byte);
            }
            uint32_t brh[8][2], brl[8][2];
#pragma unroll
            for (int nf2 = 0; nf2 < 4; nf2++) {
                uint32_t byte = (uint32_t)(wn + nf2 * 16 + (q >> 1) * 8 + idx8) * TSTRIDE
                              + ks * 32 + (q & 1) * 16;
                uint32_t r[4];
                ldsm4(r, aB + OFF_BH + byte);
                brh[nf2 * 2][0] = r[0]; brh[nf2 * 2][1] = r[1];
                brh[nf2 * 2 + 1][0] = r[2]; brh[nf2 * 2 + 1][1] = r[3];
                ldsm4(r, aB + OFF_BL + byte);
                brl[nf2 * 2][0] = r[0]; brl[nf2 * 2][1] = r[1];
                brl[nf2 * 2 + 1][0] = r[2]; brl[nf2 * 2 + 1][1] = r[3];
            }
#pragma unroll
            for (int mf = 0; mf < 4; mf++)
#pragma unroll
                for (int nf = 0; nf < 8; nf++) {
                    mma16816(acc[mf][nf], arh[mf], brh[nf]);
                    mma16816(acc[mf][nf], arh[mf], brl[nf]);
                    mma16816(acc[mf][nf], arl[mf], brh[nf]);
                }
        }
        __syncthreads();
    }

#pragma unroll
    for (int mf = 0; mf < 4; mf++) {
#pragma unroll
        for (int rh = 0; rh < 2; rh++) {
            int row = bm + wm + mf * 16 + (lane >> 2) + rh * 8;
#pragma unroll
            for (int nf = 0; nf < 8; nf++) {
                int col = bn + wn + nf * 8 + (lane & 3) * 2;
                float v0 = acc[mf][nf][rh * 2], v1 = acc[mf][nf][rh * 2 + 1];
                if (HASB) { v0 += bias[col]; v1 += bias[col + 1]; }
                if (EPI == 1) { v0 = fmaxf(v0, 0.f); v1 = fmaxf(v1, 0.f); }
                if (EPI == 2) { v0 = tanhf(v0); v1 = tanhf(v1); }
                long long idx = (long long)row * ldc + col + blockIdx.z * sC;
                if (OSPL) {
                    bf16 h0 = __float2bfloat16(v0), h1 = __float2bfloat16(v1);
                    __nv_bfloat162 hp, lp;
                    hp.x = h0; hp.y = h1;
                    lp.x = __float2bfloat16(v0 - __bfloat162float(h0));
                    lp.y = __float2bfloat16(v1 - __bfloat162float(h1));
                    *(__nv_bfloat162*)&Oh[idx] = hp;
                    *(__nv_bfloat162*)&Ol[idx] = lp;
                } else {
                    *(float2*)&C[idx] = make_float2(v0, v1);
                }
            }
        }
    }
}

// ---------------- counting + scatter (atomic, vectorized) ----------------
__global__ void zcnt_k() {
    int i = blockIdx.x * 256 + threadIdx.x;
    if (i < NBIN) g_cnt[i] = 0;
}
__global__ void zeroagg_k() {
    int i = blockIdx.x * 256 + threadIdx.x;
    if (i < NN_ * HH_) g_cat[(size_t)(i >> 8) * FF_ + (i & 255)] = 0.f;
}
__global__ void count_k(const int* __restrict__ ei, const int* __restrict__ et) {
    int e = blockIdx.x * 256 + threadIdx.x;
    if (e < EE_) atomicAdd(&g_cnt[ei[EE_ + e] * RR_ + et[e]], 1);
}
__global__ void scatter_msg_k(const int* __restrict__ ei, const int* __restrict__ et) {
    int e = blockIdx.x * 8 + (threadIdx.x >> 5);
    int lane = threadIdx.x & 31;
    if (e >= EE_) return;
    int s = ei[e], d = ei[EE_ + e], r = et[e];
    float inv = 1.0f / (float)max(g_cnt[d * RR_ + r], 1);
    const float4* p = (const float4*)(g_xw + (size_t)s * RH_ + r * HH_);
    float* o = g_cat + (size_t)d * FF_ + HH_;
#pragma unroll
    for (int i = 0; i < 2; ++i) {
        float4 v = p[lane + i * 32];
        v.x *= inv; v.y *= inv; v.z *= inv; v.w *= inv;
        red4(o + (lane + i * 32) * 4, v);
    }
}
__global__ void scatter_agg2_k(const int* __restrict__ ei) {
    int e = blockIdx.x * 8 + (threadIdx.x >> 5);
    int lane = threadIdx.x & 31;
    if (e >= EE_) return;
    int s = ei[e], d = ei[EE_ + e];
    const float4* p = (const float4*)(g_cat + (size_t)s * FF_ + HH_);
    float* o = g_cat + (size_t)d * FF_;
#pragma unroll
    for (int i = 0; i < 2; ++i) {
        float4 v = p[lane + i * 32];
        red4(o + (lane + i * 32) * 4, v);
    }
}

// ---------------- Wt = (comp x basis)^T ----------------
__global__ void __launch_bounds__(256) computeWt_k(
    const float* __restrict__ basis, const float* __restrict__ comp)
{
    __shared__ float cw[RR_ * NBASE_];
    __shared__ float T[32][33];
    int t = threadIdx.x;
    int f0 = blockIdx.x * 32, h0 = blockIdx.y * 32;
    for (int i = t; i < RR_ * NBASE_; i += 256) cw[i] = comp[i];
    __syncthreads();
    int hl = t & 31, fq = t >> 5;
    float acc[RR_][4];
#pragma unroll
    for (int r = 0; r < RR_; r++)
#pragma unroll
        for (int q = 0; q < 4; q++) acc[r][q] = 0.f;
#pragma unroll 1
    for (int b = 0; b < NBASE_; b++) {
        float bs[4];
#pragma unroll
        for (int q = 0; q < 4; q++)
            bs[q] = basis[((size_t)b * FF_ + f0 + fq * 4 + q) * HH_ + h0 + hl];
#pragma unroll
        for (int r = 0; r < RR_; r++) {
            float c = cw[r * NBASE_ + b];
#pragma unroll
            for (int q = 0; q < 4; q++) acc[r][q] = fmaf(c, bs[q], acc[r][q]);
        }
    }
#pragma unroll 1
    for (int r = 0; r < RR_; r++) {
        __syncthreads();
#pragma unroll
        for (int q = 0; q < 4; q++) T[hl][fq * 4 + q] = acc[r][q];
        __syncthreads();
        int row = t >> 3, c4 = (t & 7) * 4;
        float v0 = T[row][c4], v1 = T[row][c4 + 1], v2 = T[row][c4 + 2], v3 = T[row][c4 + 3];
        size_t o = (size_t)(r * HH_ + h0 + row) * FF_ + f0 + c4;
        bf16 b0 = __float2bfloat16(v0), b1 = __float2bfloat16(v1);
        bf16 b2 = __float2bfloat16(v2), b3 = __float2bfloat16(v3);
        __nv_bfloat162 hA, hB, lA, lB;
        hA.x = b0; hA.y = b1; hB.x = b2; hB.y = b3;
        lA.x = __float2bfloat16(v0 - __bfloat162float(b0));
        lA.y = __float2bfloat16(v1 - __bfloat162float(b1));
        lB.x = __float2bfloat16(v2 - __bfloat162float(b2));
        lB.y = __float2bfloat16(v3 - __bfloat162float(b3));
        *(__nv_bfloat162*)&g_wth[o] = hA; *(__nv_bfloat162*)&g_wth[o + 2] = hB;
        *(__nv_bfloat162*)&g_wtl[o] = lA; *(__nv_bfloat162*)&g_wtl[o + 2] = lB;
    }
}

// ---------------- misc prep ----------------
__global__ void split_k(const float* __restrict__ in, bf16* __restrict__ oh, bf16* __restrict__ ol, int n) {
    int i = blockIdx.x * 256 + threadIdx.x;
    if (i >= n) return;
    float v = in[i];
    bf16 h = __float2bfloat16(v);
    oh[i] = h;
    ol[i] = __float2bfloat16(v - __bfloat162float(h));
}
__global__ void tsplit_k(const float* __restrict__ in, bf16* __restrict__ oh, bf16* __restrict__ ol,
                         int ldi, int ldo) {
    __shared__ float t[32][33];
    int bx = blockIdx.x * 32, by = blockIdx.y * 32;
    int tx = threadIdx.x, ty = threadIdx.y;
#pragma unroll
    for (int j = 0; j < 4; ++j)
        t[ty + j * 8][tx] = in[(size_t)(by + ty + j * 8) * ldi + bx + tx];
    __syncthreads();
#pragma unroll
    for (int j = 0; j < 4; ++j) {
        float v = t[tx][ty + j * 8];
        size_t o = (size_t)(bx + ty + j * 8) * ldo + by + tx;
        bf16 h = __float2bfloat16(v);
        oh[o] = h;
        ol[o] = __float2bfloat16(v - __bfloat162float(h));
    }
}
__global__ void tspbf_k(const bf16* __restrict__ in, bf16* __restrict__ outT) {
    __shared__ bf16 t[32][33];
    const bf16* pin = in + (size_t)blockIdx.z * LL_ * DD_;
    bf16* pout = outT + (size_t)blockIdx.z * DD_ * LL_;
    int bx = blockIdx.x * 32, by = blockIdx.y * 32;
    int tx = threadIdx.x, ty = threadIdx.y;
#pragma unroll
    for (int j = 0; j < 4; ++j)
        t[ty + j * 8][tx] = pin[(size_t)(by + ty + j * 8) * DD_ + bx + tx];
    __syncthreads();
#pragma unroll
    for (int j = 0; j < 4; ++j)
        pout[(size_t)(bx + ty + j * 8) * LL_ + by + tx] = t[tx][ty + j * 8];
}
__global__ void xprep_k(const float* __restrict__ x) {
    int i = blockIdx.x * 256 + threadIdx.x;
    if (i >= NN_ * FF_) return;
    float v = x[i];
    bf16 h = __float2bfloat16(v);
    bf16 l = __float2bfloat16(v - __bfloat162float(h));
    g_xh[i] = h;
    g_xl[i] = l;
    size_t eo = (size_t)(i >> 9) * DD_ + (i & 511);
    g_emoh[eo] = h;
    g_emol[eo] = l;
}
__global__ void softmax_k() {
    const float* row = g_scores + (size_t)blockIdx.x * LL_;
    int t = threadIdx.x;
    int lane = t & 31, w = t >> 5;
    __shared__ float red[8];
    float v = row[t];
    float m = v;
#pragma unroll
    for (int o = 16; o > 0; o >>= 1) m = fmaxf(m, __shfl_xor_sync(0xffffffffu, m, o));
    if (lane == 0) red[w] = m;
    __syncthreads();
    m = red[0];
#pragma unroll
    for (int i = 1; i < 8; i++) m = fmaxf(m, red[i]);
    float e = expf(v - m);
    float s = e;
#pragma unroll
    for (int o = 16; o > 0; o >>= 1) s += __shfl_xor_sync(0xffffffffu, s, o);
    __syncthreads();
    if (lane == 0) red[w] = s;
    __syncthreads();
    s = 0.f;
#pragma unroll
    for (int i = 0; i < 8; i++) s += red[i];
    float a = e / s;
    bf16 hh = __float2bfloat16(a);
    size_t o = (size_t)blockIdx.x * LL_ + t;
    g_ah[o] = hh;
    g_al[o] = __float2bfloat16(a - __bfloat162float(hh));
}
__global__ void logits_k(const float* __restrict__ wfc, const float* __restrict__ bfc) {
    __shared__ float sw[HH_ * CC_];
    for (int i = threadIdx.x; i < HH_ * CC_; i += 256) sw[i] = wfc[i];
    __syncthreads();
    int n = blockIdx.x * 8 + (threadIdx.x >> 5);
    int lane = threadIdx.x & 31;
    const float* h = g_hidden + (size_t)n * HH_;
    float a[CC_];
#pragma unroll
    for (int c = 0; c < CC_; c++) a[c] = 0.f;
    for (int k = lane; k < HH_; k += 32) {
        float hv = h[k];
#pragma unroll
        for (int c = 0; c < CC_; c++) a[c] = fmaf(hv, sw[k * CC_ + c], a[c]);
    }
#pragma unroll
    for (int c = 0; c < CC_; c++)
#pragma unroll
        for (int o = 16; o > 0; o >>= 1) a[c] += __shfl_xor_sync(0xffffffffu, a[c], o);
    if (lane == 0)
#pragma unroll
        for (int c = 0; c < CC_; c++) g_logits[(size_t)n * CC_ + c] = a[c] + bfc[c];
}
__global__ void logsoftmax_k(float* __restrict__ out) {
    int u = blockIdx.x * 256 + threadIdx.x;
    if (u >= LL_ * CC_) return;
    int t = u / CC_, c = u % CC_;
    float vals[BB_];
    float m = -1e30f;
#pragma unroll
    for (int b = 0; b < BB_; b++) {
        vals[b] = g_logits[((size_t)(b * LL_ + t)) * CC_ + c];
        m = fmaxf(m, vals[b]);
    }
    float s = 0.f;
#pragma unroll
    for (int b = 0; b < BB_; b++) s += expf(vals[b] - m);
    float lse = m + logf(s);
#pragma unroll
    for (int b = 0; b < BB_; b++) out[((size_t)t * BB_ + b) * CC_ + c] = vals[b] - lse;
}

// ---------------- host ----------------
extern "C" void kernel_launch(void* const* d_in, const int* in_sizes, int n_in,
                              void* d_out, int out_size)
{
    const float* x      = (const float*)d_in[0];
    const int*   ei     = (const int*)  d_in[1];
    const int*   et     = (const int*)  d_in[3];
    const float* basis  = (const float*)d_in[8];
    const float* comp   = (const float*)d_in[9];
    const float* root1  = (const float*)d_in[10];
    const float* bias1  = (const float*)d_in[11];
    const float* w_rel  = (const float*)d_in[12];
    const float* b_rel  = (const float*)d_in[13];
    const float* w_root = (const float*)d_in[14];
    const float* w_att  = (const float*)d_in[15];
    const float* b_att  = (const float*)d_in[16];
    const float* w_lin  = (const float*)d_in[17];
    const float* b_lin  = (const float*)d_in[18];
    const float* w_fc   = (const float*)d_in[19];
    const float* b_fc   = (const float*)d_in[20];
    float* out = (float*)d_out;

    float *pxw, *pcat, *pscores, *phid;
    bf16 *pxh, *pxl, *pwth, *pwtl, *pr1h, *pr1l, *pw2h, *pw2l, *pwah, *pwal,
         *pwlh, *pwll, *pch, *pcl, *peh, *pel, *pXh, *pXl, *pah, *pal,
         *peTh, *peTl, *path, *patl;
    cudaGetSymbolAddress((void**)&pxw, g_xw);
    cudaGetSymbolAddress((void**)&pcat, g_cat);
    cudaGetSymbolAddress((void**)&pscores, g_scores);
    cudaGetSymbolAddress((void**)&phid, g_hidden);
    cudaGetSymbolAddress((void**)&pxh, g_xh);   cudaGetSymbolAddress((void**)&pxl, g_xl);
    cudaGetSymbolAddress((void**)&pwth, g_wth); cudaGetSymbolAddress((void**)&pwtl, g_wtl);
    cudaGetSymbolAddress((void**)&pr1h, g_r1th); cudaGetSymbolAddress((void**)&pr1l, g_r1tl);
    cudaGetSymbolAddress((void**)&pw2h, g_w2th); cudaGetSymbolAddress((void**)&pw2l, g_w2tl);
    cudaGetSymbolAddress((void**)&pwah, g_wath); cudaGetSymbolAddress((void**)&pwal, g_watl);
    cudaGetSymbolAddress((void**)&pwlh, g_wlth); cudaGetSymbolAddress((void**)&pwll, g_wltl);
    cudaGetSymbolAddress((void**)&pch, g_cath);  cudaGetSymbolAddress((void**)&pcl, g_catl);
    cudaGetSymbolAddress((void**)&peh, g_emoh);  cudaGetSymbolAddress((void**)&pel, g_emol);
    cudaGetSymbolAddress((void**)&pXh, g_Xh);    cudaGetSymbolAddress((void**)&pXl, g_Xl);
    cudaGetSymbolAddress((void**)&pah, g_ah);    cudaGetSymbolAddress((void**)&pal, g_al);
    cudaGetSymbolAddress((void**)&peTh, g_eTh);  cudaGetSymbolAddress((void**)&peTl, g_eTl);
    cudaGetSymbolAddress((void**)&path, g_atth); cudaGetSymbolAddress((void**)&patl, g_attl);

    cudaFuncSetAttribute(mmagemm_k<0,0,0>, cudaFuncAttributeMaxDynamicSharedMemorySize, SMEM_BYTES);
    cudaFuncSetAttribute(mmagemm_k<0,1,0>, cudaFuncAttributeMaxDynamicSharedMemorySize, SMEM_BYTES);
    cudaFuncSetAttribute(mmagemm_k<0,1,1>, cudaFuncAttributeMaxDynamicSharedMemorySize, SMEM_BYTES);
    cudaFuncSetAttribute(mmagemm_k<2,0,0>, cudaFuncAttributeMaxDynamicSharedMemorySize, SMEM_BYTES);
    cudaFuncSetAttribute(mmagemm_k<0,0,1>, cudaFuncAttributeMaxDynamicSharedMemorySize, SMEM_BYTES);
    cudaFuncSetAttribute(mmagemm_k<1,1,0>, cudaFuncAttributeMaxDynamicSharedMemorySize, SMEM_BYTES);

    // prep
    zcnt_k<<<NBIN / 256, 256>>>();
    zeroagg_k<<<(NN_ * HH_ + 255) / 256, 256>>>();
    count_k<<<EE_ / 256, 256>>>(ei, et);
    computeWt_k<<<dim3(FF_ / 32, HH_ / 32), 256>>>(basis, comp);
    xprep_k<<<NN_ * FF_ / 256, 256>>>(x);
    tsplit_k<<<dim3(8, 16), dim3(32, 8)>>>(root1, pr1h, pr1l, HH_, FF_);
    tsplit_k<<<dim3(8, 8),  dim3(32, 8)>>>(w_rel,  pw2h, pw2l, HH_, FF_);
    tsplit_k<<<dim3(8, 8),  dim3(32, 8)>>>(w_root, pw2h + HH_, pw2l + HH_, HH_, FF_);
    tsplit_k<<<dim3(24, 24), dim3(32, 8)>>>(w_att, pwah, pwal, DD_, DD_);
    tsplit_k<<<dim3(8, 24),  dim3(32, 8)>>>(w_lin, pwlh, pwll, HH_, DD_);

    // xw = x @ Wcat
    mmagemm_k<0,0,0><<<dim3(16, 64), 256, SMEM_BYTES>>>(
        pxh, pxl, pwth, pwtl, pxw, nullptr, nullptr, nullptr, FF_, RH_, 0, 0, 0);
    // out1 base = x @ root1 + bias1 -> g_cat[:,256:512] (fp32)
    mmagemm_k<0,1,0><<<dim3(1, 64), 256, SMEM_BYTES>>>(
        pxh, pxl, pr1h, pr1l, pcat + HH_, nullptr, nullptr, bias1, FF_, FF_, 0, 0, 0);
    // atomic scatters (v4 reductions)
    scatter_msg_k<<<EE_ / 8, 256>>>(ei, et);
    scatter_agg2_k<<<EE_ / 8, 256>>>(ei);
    // split cat; out2 = [agg2|out1] @ [w_rel;w_root] + b_rel -> emotions[:,512:768] (bf16 split)
    split_k<<<NN_ * FF_ / 256, 256>>>(pcat, pch, pcl, NN_ * FF_);
    mmagemm_k<0,1,1><<<dim3(1, 64), 256, SMEM_BYTES>>>(
        pch, pcl, pw2h, pw2l, nullptr, peh + FF_, pel + FF_, b_rel, FF_, DD_, 0, 0, 0);
    // X = emotions @ w_att + b_att (bf16 split out)
    mmagemm_k<0,1,1><<<dim3(3, 64), 256, SMEM_BYTES>>>(
        peh, pel, pwah, pwal, nullptr, pXh, pXl, b_att, DD_, DD_, 0, 0, 0);
    // scores = tanh(X_b @ emotions_b^T)
    mmagemm_k<2,0,0><<<dim3(1, 2, BB_), 256, SMEM_BYTES>>>(
        pXh, pXl, peh, pel, pscores, nullptr, nullptr, nullptr, DD_, LL_,
        (long long)LL_ * DD_, (long long)LL_ * DD_, (long long)LL_ * LL_);
    // softmax (writes split attention weights)
    softmax_k<<<BB_ * LL_, LL_>>>();
    // emotions^T per batch (bf16)
    tspbf_k<<<dim3(24, 8, BB_), dim3(32, 8)>>>(peh, peTh);
    tspbf_k<<<dim3(24, 8, BB_), dim3(32, 8)>>>(pel, peTl);
    // att = a_b @ emotions_b (bf16 split out)
    mmagemm_k<0,0,1><<<dim3(3, 2, BB_), 256, SMEM_BYTES>>>(
        pah, pal, peTh, peTl, nullptr, path, patl, nullptr, LL_, DD_,
        (long long)LL_ * LL_, (long long)DD_ * LL_, (long long)LL_ * DD_);
    // hidden = relu(att @ w_lin + b_lin)
    mmagemm_k<1,1,0><<<dim3(1, 64), 256, SMEM_BYTES>>>(
        path, patl, pwlh, pwll, phid, nullptr, nullptr, b_lin, DD_, HH_, 0, 0, 0);
    // logits + log_softmax
    logits_k<<<NN_ / 8, 256>>>(w_fc, b_fc);
    logsoftmax_k<<<(LL_ * CC_ + 255) / 256, 256>>>(out);
}

// round 15
// speedup vs baseline: 1.0934x; 1.0934x over previous
#include <cuda_runtime.h>
#include <cuda_bf16.h>
#include <stdint.h>
#include <math.h>

#define NN_ 8192
#define FF_ 512
#define HH_ 256
#define RR_ 16
#define BB_ 32
#define LL_ 256
#define CC_ 7
#define EE_ 262144
#define NBASE_ 30
#define DD_ 768
#define RH_ 4096
#define NBIN (NN_ * RR_)
#define NW_ (RH_ + HH_)          // Wcat rows + root1 rows (fused B)

typedef __nv_bfloat16 bf16;

// ---------------- scratch ----------------
__device__ __align__(16) float g_xw[(size_t)NN_ * RH_];
__device__ int   g_cnt[NBIN];
__device__ __align__(16) float g_cat[NN_ * FF_];      // [:,0:256]=agg2 [:,256:512]=out1
__device__ __align__(16) float g_scores[BB_ * LL_ * LL_];
__device__ __align__(16) float g_hidden[NN_ * HH_];
__device__ __align__(16) float g_logits[NN_ * CC_];

__device__ __align__(16) bf16 g_xh[NN_*FF_],   g_xl[NN_*FF_];
__device__ __align__(16) bf16 g_wth[NW_*FF_],  g_wtl[NW_*FF_];   // [Wcat^T ; root1^T]
__device__ __align__(16) bf16 g_w2th[HH_*FF_], g_w2tl[HH_*FF_];
__device__ __align__(16) bf16 g_wath[DD_*DD_], g_watl[DD_*DD_];
__device__ __align__(16) bf16 g_wlth[HH_*DD_], g_wltl[HH_*DD_];
__device__ __align__(16) bf16 g_cath[NN_*FF_], g_catl[NN_*FF_];
__device__ __align__(16) bf16 g_emoh[NN_*DD_], g_emol[NN_*DD_];
__device__ __align__(16) bf16 g_Xh[NN_*DD_],   g_Xl[NN_*DD_];
__device__ __align__(16) bf16 g_ah[BB_*LL_*LL_], g_al[BB_*LL_*LL_];
__device__ __align__(16) bf16 g_eTh[BB_*DD_*LL_], g_eTl[BB_*DD_*LL_];
__device__ __align__(16) bf16 g_atth[NN_*DD_], g_attl[NN_*DD_];

// ---------------- helpers ----------------
__device__ __forceinline__ uint32_t smem_u32(const void* p) {
    uint32_t a;
    asm("{ .reg .u64 t; cvta.to.shared.u64 t, %1; cvt.u32.u64 %0, t; }" : "=r"(a) : "l"(p));
    return a;
}
__device__ __forceinline__ void cpasync16(uint32_t dst, const void* src) {
    asm volatile("cp.async.cg.shared.global [%0], [%1], 16;" :: "r"(dst), "l"(src));
}
__device__ __forceinline__ void ldsm4(uint32_t* r, uint32_t addr) {
    asm volatile("ldmatrix.sync.aligned.m8n8.x4.shared.b16 {%0,%1,%2,%3}, [%4];"
        : "=r"(r[0]), "=r"(r[1]), "=r"(r[2]), "=r"(r[3]) : "r"(addr));
}
__device__ __forceinline__ void mma16816(float* c, const uint32_t* a, const uint32_t* b) {
    asm volatile("mma.sync.aligned.m16n8k16.row.col.f32.bf16.bf16.f32 "
        "{%0,%1,%2,%3},{%4,%5,%6,%7},{%8,%9},{%0,%1,%2,%3};"
        : "+f"(c[0]), "+f"(c[1]), "+f"(c[2]), "+f"(c[3])
        : "r"(a[0]), "r"(a[1]), "r"(a[2]), "r"(a[3]), "r"(b[0]), "r"(b[1]));
}
__device__ __forceinline__ void red4(float* p, float4 v) {
    asm volatile("red.global.add.v4.f32 [%0], {%1,%2,%3,%4};"
        :: "l"(p), "f"(v.x), "f"(v.y), "f"(v.z), "f"(v.w) : "memory");
}

// ---------------- HMMA GEMM: C[128x128/CTA] = (Ah+Al) @ (Bh+Bl)^T ----------------
// 3-stage cp.async pipeline; warp tile 64x32.
// XWF: fused xw+out1 epilogue (col<4096 -> g_xw; col>=4096 -> g_cat[:,256:512]+bias)
#define TSTRIDE 80
#define TILE_B  10240
#define STAGE_B 40960
#define SMEM_BYTES (3 * STAGE_B)

template <int EPI, int HASB, int OSPL, int XWF>
__global__ void __launch_bounds__(256, 1) mmagemm_k(
    const bf16* __restrict__ Ah, const bf16* __restrict__ Al,
    const bf16* __restrict__ Bh, const bf16* __restrict__ Bl,
    float* __restrict__ C, bf16* __restrict__ Oh, bf16* __restrict__ Ol,
    const float* __restrict__ bias,
    int K, int ldc, long long sA, long long sB, long long sC)
{
    extern __shared__ __align__(16) char smem[];
    const int tid = threadIdx.x, lane = tid & 31, wid = tid >> 5;
    const int wm = (wid >> 2) * 64, wn = (wid & 3) * 32;
    const int bm = blockIdx.y << 7, bn = blockIdx.x << 7;
    Ah += blockIdx.z * sA;  Al += blockIdx.z * sA;
    Bh += blockIdx.z * sB;  Bl += blockIdx.z * sB;
    const uint32_t sbase = smem_u32(smem);
    const size_t rsk = (size_t)K * 2;

    float acc[4][4][4];
#pragma unroll
    for (int i = 0; i < 4; i++)
#pragma unroll
        for (int j = 0; j < 4; j++)
#pragma unroll
            for (int r = 0; r < 4; r++) acc[i][j][r] = 0.f;

    const char* pA0 = (const char*)Ah + (size_t)bm * rsk;
    const char* pA1 = (const char*)Al + (size_t)bm * rsk;
    const char* pB0 = (const char*)Bh + (size_t)bn * rsk;
    const char* pB1 = (const char*)Bl + (size_t)bn * rsk;

    // k0 in ELEMENTS (multiple of 32)
    auto issue = [&](int stage, int k0) {
        uint32_t d0 = sbase + stage * STAGE_B;
#pragma unroll
        for (int i = 0; i < 2; i++) {
            int task = tid + i * 256;
            int row = task >> 2, ch = task & 3;
            uint32_t doff = row * TSTRIDE + ch * 16;
            size_t goff = (size_t)row * rsk + (size_t)k0 * 2 + ch * 16;
            cpasync16(d0 + doff,              pA0 + goff);
            cpasync16(d0 + TILE_B + doff,     pA1 + goff);
            cpasync16(d0 + 2 * TILE_B + doff, pB0 + goff);
            cpasync16(d0 + 3 * TILE_B + doff, pB1 + goff);
        }
        asm volatile("cp.async.commit_group;" ::: "memory");
    };

    const int NK = K >> 5;
    issue(0, 0);
    if (NK > 1) issue(1, 32);
#pragma unroll 1
    for (int k = 0; k < NK; k++) {
        if (k + 1 < NK) {
            asm volatile("cp.async.wait_group 1;" ::: "memory");
        } else {
            asm volatile("cp.async.wait_group 0;" ::: "memory");
        }
        __syncthreads();
        if (k + 2 < NK) issue((k + 2) % 3, (k + 2) << 5);
        const uint32_t aB = sbase + (k % 3) * STAGE_B;
        const int idx8 = lane & 7, q = lane >> 3;
#pragma unroll
        for (int ks = 0; ks < 2; ks++) {
            uint32_t arh[4][4], arl[4][4];
#pragma unroll
            for (int mf = 0; mf < 4; mf++) {
                uint32_t byte = (uint32_t)(wm + mf * 16 + (q & 1) * 8 + idx8) * TSTRIDE
                              + ks * 32 + (q >> 1) * 16;
                ldsm4(arh[mf], aB + byte);
                ldsm4(arl[mf], aB + TILE_B + byte);
            }
            uint32_t brh[4][2], brl[4][2];
#pragma unroll
            for (int nf2 = 0; nf2 < 2; nf2++) {
                uint32_t byte = (uint32_t)(wn + nf2 * 16 + (q >> 1) * 8 + idx8) * TSTRIDE
                              + ks * 32 + (q & 1) * 16;
                uint32_t r[4];
                ldsm4(r, aB + 2 * TILE_B + byte);
                brh[nf2 * 2][0] = r[0]; brh[nf2 * 2][1] = r[1];
                brh[nf2 * 2 + 1][0] = r[2]; brh[nf2 * 2 + 1][1] = r[3];
                ldsm4(r, aB + 3 * TILE_B + byte);
                brl[nf2 * 2][0] = r[0]; brl[nf2 * 2][1] = r[1];
                brl[nf2 * 2 + 1][0] = r[2]; brl[nf2 * 2 + 1][1] = r[3];
            }
#pragma unroll
            for (int mf = 0; mf < 4; mf++)
#pragma unroll
                for (int nf = 0; nf < 4; nf++) {
                    mma16816(acc[mf][nf], arh[mf], brh[nf]);
                    mma16816(acc[mf][nf], arh[mf], brl[nf]);
                    mma16816(acc[mf][nf], arl[mf], brh[nf]);
                }
        }
        __syncthreads();
    }

#pragma unroll
    for (int mf = 0; mf < 4; mf++) {
#pragma unroll
        for (int rh = 0; rh < 2; rh++) {
            int row = bm + wm + mf * 16 + (lane >> 2) + rh * 8;
#pragma unroll
            for (int nf = 0; nf < 4; nf++) {
                int col = bn + wn + nf * 8 + (lane & 3) * 2;
                float v0 = acc[mf][nf][rh * 2], v1 = acc[mf][nf][rh * 2 + 1];
                if (XWF) {
                    if (col < RH_) {
                        *(float2*)&C[(long long)row * RH_ + col] = make_float2(v0, v1);
                    } else {
                        int cc = col - RH_;
                        v0 += bias[cc]; v1 += bias[cc + 1];
                        *(float2*)&g_cat[(size_t)row * FF_ + HH_ + cc] = make_float2(v0, v1);
                    }
                    continue;
                }
                if (HASB) { v0 += bias[col]; v1 += bias[col + 1]; }
                if (EPI == 1) { v0 = fmaxf(v0, 0.f); v1 = fmaxf(v1, 0.f); }
                if (EPI == 2) { v0 = tanhf(v0); v1 = tanhf(v1); }
                long long idx = (long long)row * ldc + col + blockIdx.z * sC;
                if (OSPL) {
                    bf16 h0 = __float2bfloat16(v0), h1 = __float2bfloat16(v1);
                    __nv_bfloat162 hp, lp;
                    hp.x = h0; hp.y = h1;
                    lp.x = __float2bfloat16(v0 - __bfloat162float(h0));
                    lp.y = __float2bfloat16(v1 - __bfloat162float(h1));
                    *(__nv_bfloat162*)&Oh[idx] = hp;
                    *(__nv_bfloat162*)&Ol[idx] = lp;
                } else {
                    *(float2*)&C[idx] = make_float2(v0, v1);
                }
            }
        }
    }
}

// ---------------- counting + scatter ----------------
__global__ void zcnt_k() {
    int i = blockIdx.x * 256 + threadIdx.x;
    if (i < NBIN) g_cnt[i] = 0;
}
__global__ void zeroagg_k() {
    int i = blockIdx.x * 256 + threadIdx.x;
    if (i < NN_ * HH_) g_cat[(size_t)(i >> 8) * FF_ + (i & 255)] = 0.f;
}
__global__ void count_k(const int* __restrict__ ei, const int* __restrict__ et) {
    int e = blockIdx.x * 256 + threadIdx.x;
    if (e < EE_) atomicAdd(&g_cnt[ei[EE_ + e] * RR_ + et[e]], 1);
}
__global__ void scatter_msg_k(const int* __restrict__ ei, const int* __restrict__ et) {
    int e = blockIdx.x * 8 + (threadIdx.x >> 5);
    int lane = threadIdx.x & 31;
    if (e >= EE_) return;
    int s = ei[e], d = ei[EE_ + e], r = et[e];
    float inv = 1.0f / (float)max(g_cnt[d * RR_ + r], 1);
    const float4* p = (const float4*)(g_xw + (size_t)s * RH_ + r * HH_);
    float* o = g_cat + (size_t)d * FF_ + HH_;
#pragma unroll
    for (int i = 0; i < 2; ++i) {
        float4 v = p[lane + i * 32];
        v.x *= inv; v.y *= inv; v.z *= inv; v.w *= inv;
        red4(o + (lane + i * 32) * 4, v);
    }
}
__global__ void scatter_agg2_k(const int* __restrict__ ei) {
    int e = blockIdx.x * 8 + (threadIdx.x >> 5);
    int lane = threadIdx.x & 31;
    if (e >= EE_) return;
    int s = ei[e], d = ei[EE_ + e];
    const float4* p = (const float4*)(g_cat + (size_t)s * FF_ + HH_);
    float* o = g_cat + (size_t)d * FF_;
#pragma unroll
    for (int i = 0; i < 2; ++i) {
        float4 v = p[lane + i * 32];
        red4(o + (lane + i * 32) * 4, v);
    }
}

// ---------------- Wt = (comp x basis)^T ----------------
__global__ void __launch_bounds__(256) computeWt_k(
    const float* __restrict__ basis, const float* __restrict__ comp)
{
    __shared__ float cw[RR_ * NBASE_];
    __shared__ float T[32][33];
    int t = threadIdx.x;
    int f0 = blockIdx.x * 32, h0 = blockIdx.y * 32;
    for (int i = t; i < RR_ * NBASE_; i += 256) cw[i] = comp[i];
    __syncthreads();
    int hl = t & 31, fq = t >> 5;
    float acc[RR_][4];
#pragma unroll
    for (int r = 0; r < RR_; r++)
#pragma unroll
        for (int q = 0; q < 4; q++) acc[r][q] = 0.f;
#pragma unroll 1
    for (int b = 0; b < NBASE_; b++) {
        float bs[4];
#pragma unroll
        for (int q = 0; q < 4; q++)
            bs[q] = basis[((size_t)b * FF_ + f0 + fq * 4 + q) * HH_ + h0 + hl];
#pragma unroll
        for (int r = 0; r < RR_; r++) {
            float c = cw[r * NBASE_ + b];
#pragma unroll
            for (int q = 0; q < 4; q++) acc[r][q] = fmaf(c, bs[q], acc[r][q]);
        }
    }
#pragma unroll 1
    for (int r = 0; r < RR_; r++) {
        __syncthreads();
#pragma unroll
        for (int q = 0; q < 4; q++) T[hl][fq * 4 + q] = acc[r][q];
        __syncthreads();
        int row = t >> 3, c4 = (t & 7) * 4;
        float v0 = T[row][c4], v1 = T[row][c4 + 1], v2 = T[row][c4 + 2], v3 = T[row][c4 + 3];
        size_t o = (size_t)(r * HH_ + h0 + row) * FF_ + f0 + c4;
        bf16 b0 = __float2bfloat16(v0), b1 = __float2bfloat16(v1);
        bf16 b2 = __float2bfloat16(v2), b3 = __float2bfloat16(v3);
        __nv_bfloat162 hA, hB, lA, lB;
        hA.x = b0; hA.y = b1; hB.x = b2; hB.y = b3;
        lA.x = __float2bfloat16(v0 - __bfloat162float(b0));
        lA.y = __float2bfloat16(v1 - __bfloat162float(b1));
        lB.x = __float2bfloat16(v2 - __bfloat162float(b2));
        lB.y = __float2bfloat16(v3 - __bfloat162float(b3));
        *(__nv_bfloat162*)&g_wth[o] = hA; *(__nv_bfloat162*)&g_wth[o + 2] = hB;
        *(__nv_bfloat162*)&g_wtl[o] = lA; *(__nv_bfloat162*)&g_wtl[o + 2] = lB;
    }
}

// ---------------- misc prep ----------------
__global__ void split_k(const float* __restrict__ in, bf16* __restrict__ oh, bf16* __restrict__ ol, int n) {
    int i = blockIdx.x * 256 + threadIdx.x;
    if (i >= n) return;
    float v = in[i];
    bf16 h = __float2bfloat16(v);
    oh[i] = h;
    ol[i] = __float2bfloat16(v - __bfloat162float(h));
}
__global__ void tsplit_k(const float* __restrict__ in, bf16* __restrict__ oh, bf16* __restrict__ ol,
                         int ldi, int ldo) {
    __shared__ float t[32][33];
    int bx = blockIdx.x * 32, by = blockIdx.y * 32;
    int tx = threadIdx.x, ty = threadIdx.y;
#pragma unroll
    for (int j = 0; j < 4; ++j)
        t[ty + j * 8][tx] = in[(size_t)(by + ty + j * 8) * ldi + bx + tx];
    __syncthreads();
#pragma unroll
    for (int j = 0; j < 4; ++j) {
        float v = t[tx][ty + j * 8];
        size_t o = (size_t)(bx + ty + j * 8) * ldo + by + tx;
        bf16 h = __float2bfloat16(v);
        oh[o] = h;
        ol[o] = __float2bfloat16(v - __bfloat162float(h));
    }
}
__global__ void tspbf_k(const bf16* __restrict__ in, bf16* __restrict__ outT) {
    __shared__ bf16 t[32][33];
    const bf16* pin = in + (size_t)blockIdx.z * LL_ * DD_;
    bf16* pout = outT + (size_t)blockIdx.z * DD_ * LL_;
    int bx = blockIdx.x * 32, by = blockIdx.y * 32;
    int tx = threadIdx.x, ty = threadIdx.y;
#pragma unroll
    for (int j = 0; j < 4; ++j)
        t[ty + j * 8][tx] = pin[(size_t)(by + ty + j * 8) * DD_ + bx + tx];
    __syncthreads();
#pragma unroll
    for (int j = 0; j < 4; ++j)
        pout[(size_t)(bx + ty + j * 8) * LL_ + by + tx] = t[tx][ty + j * 8];
}
__global__ void xprep_k(const float* __restrict__ x) {
    int i = blockIdx.x * 256 + threadIdx.x;
    if (i >= NN_ * FF_) return;
    float v = x[i];
    bf16 h = __float2bfloat16(v);
    bf16 l = __float2bfloat16(v - __bfloat162float(h));
    g_xh[i] = h;
    g_xl[i] = l;
    size_t eo = (size_t)(i >> 9) * DD_ + (i & 511);
    g_emoh[eo] = h;
    g_emol[eo] = l;
}
__global__ void softmax_k() {
    const float* row = g_scores + (size_t)blockIdx.x * LL_;
    int t = threadIdx.x;
    int lane = t & 31, w = t >> 5;
    __shared__ float red[8];
    float v = row[t];
    float m = v;
#pragma unroll
    for (int o = 16; o > 0; o >>= 1) m = fmaxf(m, __shfl_xor_sync(0xffffffffu, m, o));
    if (lane == 0) red[w] = m;
    __syncthreads();
    m = red[0];
#pragma unroll
    for (int i = 1; i < 8; i++) m = fmaxf(m, red[i]);
    float e = expf(v - m);
    float s = e;
#pragma unroll
    for (int o = 16; o > 0; o >>= 1) s += __shfl_xor_sync(0xffffffffu, s, o);
    __syncthreads();
    if (lane == 0) red[w] = s;
    __syncthreads();
    s = 0.f;
#pragma unroll
    for (int i = 0; i < 8; i++) s += red[i];
    float a = e / s;
    bf16 hh = __float2bfloat16(a);
    size_t o = (size_t)blockIdx.x * LL_ + t;
    g_ah[o] = hh;
    g_al[o] = __float2bfloat16(a - __bfloat162float(hh));
}
__global__ void logits_k(const float* __restrict__ wfc, const float* __restrict__ bfc) {
    __shared__ float sw[HH_ * CC_];
    for (int i = threadIdx.x; i < HH_ * CC_; i += 256) sw[i] = wfc[i];
    __syncthreads();
    int n = blockIdx.x * 8 + (threadIdx.x >> 5);
    int lane = threadIdx.x & 31;
    const float* h = g_hidden + (size_t)n * HH_;
    float a[CC_];
#pragma unroll
    for (int c = 0; c < CC_; c++) a[c] = 0.f;
    for (int k = lane; k < HH_; k += 32) {
        float hv = h[k];
#pragma unroll
        for (int c = 0; c < CC_; c++) a[c] = fmaf(hv, sw[k * CC_ + c], a[c]);
    }
#pragma unroll
    for (int c = 0; c < CC_; c++)
#pragma unroll
        for (int o = 16; o > 0; o >>= 1) a[c] += __shfl_xor_sync(0xffffffffu, a[c], o);
    if (lane == 0)
#pragma unroll
        for (int c = 0; c < CC_; c++) g_logits[(size_t)n * CC_ + c] = a[c] + bfc[c];
}
__global__ void logsoftmax_k(float* __restrict__ out) {
    int u = blockIdx.x * 256 + threadIdx.x;
    if (u >= LL_ * CC_) return;
    int t = u / CC_, c = u % CC_;
    float vals[BB_];
    float m = -1e30f;
#pragma unroll
    for (int b = 0; b < BB_; b++) {
        vals[b] = g_logits[((size_t)(b * LL_ + t)) * CC_ + c];
        m = fmaxf(m, vals[b]);
    }
    float s = 0.f;
#pragma unroll
    for (int b = 0; b < BB_; b++) s += expf(vals[b] - m);
    float lse = m + logf(s);
#pragma unroll
    for (int b = 0; b < BB_; b++) out[((size_t)t * BB_ + b) * CC_ + c] = vals[b] - lse;
}

// ---------------- host ----------------
extern "C" void kernel_launch(void* const* d_in, const int* in_sizes, int n_in,
                              void* d_out, int out_size)
{
    const float* x      = (const float*)d_in[0];
    const int*   ei     = (const int*)  d_in[1];
    const int*   et     = (const int*)  d_in[3];
    const float* basis  = (const float*)d_in[8];
    const float* comp   = (const float*)d_in[9];
    const float* root1  = (const float*)d_in[10];
    const float* bias1  = (const float*)d_in[11];
    const float* w_rel  = (const float*)d_in[12];
    const float* b_rel  = (const float*)d_in[13];
    const float* w_root = (const float*)d_in[14];
    const float* w_att  = (const float*)d_in[15];
    const float* b_att  = (const float*)d_in[16];
    const float* w_lin  = (const float*)d_in[17];
    const float* b_lin  = (const float*)d_in[18];
    const float* w_fc   = (const float*)d_in[19];
    const float* b_fc   = (const float*)d_in[20];
    float* out = (float*)d_out;

    float *pxw, *pcat, *pscores, *phid;
    bf16 *pxh, *pxl, *pwth, *pwtl, *pw2h, *pw2l, *pwah, *pwal,
         *pwlh, *pwll, *pch, *pcl, *peh, *pel, *pXh, *pXl, *pah, *pal,
         *peTh, *peTl, *path, *patl;
    cudaGetSymbolAddress((void**)&pxw, g_xw);
    cudaGetSymbolAddress((void**)&pcat, g_cat);
    cudaGetSymbolAddress((void**)&pscores, g_scores);
    cudaGetSymbolAddress((void**)&phid, g_hidden);
    cudaGetSymbolAddress((void**)&pxh, g_xh);   cudaGetSymbolAddress((void**)&pxl, g_xl);
    cudaGetSymbolAddress((void**)&pwth, g_wth); cudaGetSymbolAddress((void**)&pwtl, g_wtl);
    cudaGetSymbolAddress((void**)&pw2h, g_w2th); cudaGetSymbolAddress((void**)&pw2l, g_w2tl);
    cudaGetSymbolAddress((void**)&pwah, g_wath); cudaGetSymbolAddress((void**)&pwal, g_watl);
    cudaGetSymbolAddress((void**)&pwlh, g_wlth); cudaGetSymbolAddress((void**)&pwll, g_wltl);
    cudaGetSymbolAddress((void**)&pch, g_cath);  cudaGetSymbolAddress((void**)&pcl, g_catl);
    cudaGetSymbolAddress((void**)&peh, g_emoh);  cudaGetSymbolAddress((void**)&pel, g_emol);
    cudaGetSymbolAddress((void**)&pXh, g_Xh);    cudaGetSymbolAddress((void**)&pXl, g_Xl);
    cudaGetSymbolAddress((void**)&pah, g_ah);    cudaGetSymbolAddress((void**)&pal, g_al);
    cudaGetSymbolAddress((void**)&peTh, g_eTh);  cudaGetSymbolAddress((void**)&peTl, g_eTl);
    cudaGetSymbolAddress((void**)&path, g_atth); cudaGetSymbolAddress((void**)&patl, g_attl);

    cudaFuncSetAttribute(mmagemm_k<0,0,0,1>, cudaFuncAttributeMaxDynamicSharedMemorySize, SMEM_BYTES);
    cudaFuncSetAttribute(mmagemm_k<0,1,1,0>, cudaFuncAttributeMaxDynamicSharedMemorySize, SMEM_BYTES);
    cudaFuncSetAttribute(mmagemm_k<2,0,0,0>, cudaFuncAttributeMaxDynamicSharedMemorySize, SMEM_BYTES);
    cudaFuncSetAttribute(mmagemm_k<0,0,1,0>, cudaFuncAttributeMaxDynamicSharedMemorySize, SMEM_BYTES);
    cudaFuncSetAttribute(mmagemm_k<1,1,0,0>, cudaFuncAttributeMaxDynamicSharedMemorySize, SMEM_BYTES);

    // prep (serial, default stream)
    zcnt_k<<<NBIN / 256, 256>>>();
    zeroagg_k<<<(NN_ * HH_ + 255) / 256, 256>>>();
    count_k<<<EE_ / 256, 256>>>(ei, et);
    computeWt_k<<<dim3(FF_ / 32, HH_ / 32), 256>>>(basis, comp);
    xprep_k<<<NN_ * FF_ / 256, 256>>>(x);
    // root1^T appended to Wcat^T rows [4096:4352)
    tsplit_k<<<dim3(8, 16), dim3(32, 8)>>>(root1, pwth + (size_t)RH_ * FF_, pwtl + (size_t)RH_ * FF_, HH_, FF_);
    tsplit_k<<<dim3(8, 8),  dim3(32, 8)>>>(w_rel,  pw2h, pw2l, HH_, FF_);
    tsplit_k<<<dim3(8, 8),  dim3(32, 8)>>>(w_root, pw2h + HH_, pw2l + HH_, HH_, FF_);
    tsplit_k<<<dim3(24, 24), dim3(32, 8)>>>(w_att, pwah, pwal, DD_, DD_);
    tsplit_k<<<dim3(8, 24),  dim3(32, 8)>>>(w_lin, pwlh, pwll, HH_, DD_);

    // fused: xw = x @ Wcat  AND  out1 base = x @ root1 + bias1
    mmagemm_k<0,0,0,1><<<dim3(NW_ / 128, 64), 256, SMEM_BYTES>>>(
        pxh, pxl, pwth, pwtl, pxw, nullptr, nullptr, bias1, FF_, RH_, 0, 0, 0);
    // atomic scatters
    scatter_msg_k<<<EE_ / 8, 256>>>(ei, et);
    scatter_agg2_k<<<EE_ / 8, 256>>>(ei);
    // split cat; out2 = [agg2|out1] @ [w_rel;w_root] + b_rel -> emotions[:,512:768] (bf16 split)
    split_k<<<NN_ * FF_ / 256, 256>>>(pcat, pch, pcl, NN_ * FF_);
    mmagemm_k<0,1,1,0><<<dim3(2, 64), 256, SMEM_BYTES>>>(
        pch, pcl, pw2h, pw2l, nullptr, peh + FF_, pel + FF_, b_rel, FF_, DD_, 0, 0, 0);
    // X = emotions @ w_att + b_att (bf16 split out)
    mmagemm_k<0,1,1,0><<<dim3(6, 64), 256, SMEM_BYTES>>>(
        peh, pel, pwah, pwal, nullptr, pXh, pXl, b_att, DD_, DD_, 0, 0, 0);
    // scores = tanh(X_b @ emotions_b^T)
    mmagemm_k<2,0,0,0><<<dim3(2, 2, BB_), 256, SMEM_BYTES>>>(
        pXh, pXl, peh, pel, pscores, nullptr, nullptr, nullptr, DD_, LL_,
        (long long)LL_ * DD_, (long long)LL_ * DD_, (long long)LL_ * LL_);
    softmax_k<<<BB_ * LL_, LL_>>>();
    // emotions^T per batch (bf16)
    tspbf_k<<<dim3(24, 8, BB_), dim3(32, 8)>>>(peh, peTh);
    tspbf_k<<<dim3(24, 8, BB_), dim3(32, 8)>>>(pel, peTl);
    // att = a_b @ emotions_b (bf16 split out)
    mmagemm_k<0,0,1,0><<<dim3(6, 2, BB_), 256, SMEM_BYTES>>>(
        pah, pal, peTh, peTl, nullptr, path, patl, nullptr, LL_, DD_,
        (long long)LL_ * LL_, (long long)DD_ * LL_, (long long)LL_ * DD_);
    // hidden = relu(att @ w_lin + b_lin)
    mmagemm_k<1,1,0,0><<<dim3(2, 64), 256, SMEM_BYTES>>>(
        path, patl, pwlh, pwll, phid, nullptr, nullptr, b_lin, DD_, HH_, 0, 0, 0);
    // logits + log_softmax
    logits_k<<<NN_ / 8, 256>>>(w_fc, b_fc);
    logsoftmax_k<<<(LL_ * CC_ + 255) / 256, 256>>>(out);
}

// round 16
// speedup vs baseline: 1.1956x; 1.0934x over previous
#include <cuda_runtime.h>
#include <cuda_bf16.h>
#include <stdint.h>
#include <math.h>

#define NN_ 8192
#define FF_ 512
#define HH_ 256
#define RR_ 16
#define BB_ 32
#define LL_ 256
#define CC_ 7
#define EE_ 262144
#define NBASE_ 30
#define DD_ 768
#define RH_ 4096
#define NBIN (NN_ * RR_)
#define NW_ (RH_ + HH_)          // Wcat rows + root1 rows (fused B)

typedef __nv_bfloat16 bf16;

// ---------------- scratch ----------------
__device__ __align__(16) float g_xw[(size_t)NN_ * RH_];
__device__ int   g_cnt[NBIN];
__device__ __align__(16) float g_cat[NN_ * FF_];      // [:,0:256]=agg2 [:,256:512]=out1
__device__ __align__(16) float g_scores[BB_ * LL_ * LL_];
__device__ __align__(16) float g_hidden[NN_ * HH_];
__device__ __align__(16) float g_logits[NN_ * CC_];

__device__ __align__(16) bf16 g_xh[NN_*FF_],   g_xl[NN_*FF_];
__device__ __align__(16) bf16 g_wth[NW_*FF_],  g_wtl[NW_*FF_];   // [Wcat^T ; root1^T]
__device__ __align__(16) bf16 g_w2th[HH_*FF_], g_w2tl[HH_*FF_];
__device__ __align__(16) bf16 g_wath[DD_*DD_], g_watl[DD_*DD_];
__device__ __align__(16) bf16 g_wlth[HH_*DD_], g_wltl[HH_*DD_];
__device__ __align__(16) bf16 g_cath[NN_*FF_], g_catl[NN_*FF_];
__device__ __align__(16) bf16 g_emoh[NN_*DD_], g_emol[NN_*DD_];
__device__ __align__(16) bf16 g_Xh[NN_*DD_],   g_Xl[NN_*DD_];
__device__ __align__(16) bf16 g_ah[BB_*LL_*LL_], g_al[BB_*LL_*LL_];
__device__ __align__(16) bf16 g_eTh[BB_*DD_*LL_], g_eTl[BB_*DD_*LL_];
__device__ __align__(16) bf16 g_atth[NN_*DD_], g_attl[NN_*DD_];

// ---------------- helpers ----------------
__device__ __forceinline__ uint32_t smem_u32(const void* p) {
    uint32_t a;
    asm("{ .reg .u64 t; cvta.to.shared.u64 t, %1; cvt.u32.u64 %0, t; }" : "=r"(a) : "l"(p));
    return a;
}
__device__ __forceinline__ void cpasync16(uint32_t dst, const void* src) {
    asm volatile("cp.async.cg.shared.global [%0], [%1], 16;" :: "r"(dst), "l"(src));
}
__device__ __forceinline__ void ldsm4(uint32_t* r, uint32_t addr) {
    asm volatile("ldmatrix.sync.aligned.m8n8.x4.shared.b16 {%0,%1,%2,%3}, [%4];"
        : "=r"(r[0]), "=r"(r[1]), "=r"(r[2]), "=r"(r[3]) : "r"(addr));
}
__device__ __forceinline__ void mma16816(float* c, const uint32_t* a, const uint32_t* b) {
    asm volatile("mma.sync.aligned.m16n8k16.row.col.f32.bf16.bf16.f32 "
        "{%0,%1,%2,%3},{%4,%5,%6,%7},{%8,%9},{%0,%1,%2,%3};"
        : "+f"(c[0]), "+f"(c[1]), "+f"(c[2]), "+f"(c[3])
        : "r"(a[0]), "r"(a[1]), "r"(a[2]), "r"(a[3]), "r"(b[0]), "r"(b[1]));
}
__device__ __forceinline__ void red4(float* p, float4 v) {
    asm volatile("red.global.add.v4.f32 [%0], {%1,%2,%3,%4};"
        :: "l"(p), "f"(v.x), "f"(v.y), "f"(v.z), "f"(v.w) : "memory");
}

// ---------------- HMMA GEMM: C[128x128/CTA] = (Ah+Al) @ (Bh+Bl)^T ----------------
// 2-stage cp.async pipeline; warp tile 64x32; 2 CTAs/SM (occupancy-driven).
// XWF: fused xw+out1 epilogue (col<4096 -> g_xw; col>=4096 -> g_cat[:,256:512]+bias)
#define TSTRIDE 80
#define TILE_B  10240
#define STAGE_B 40960
#define SMEM_BYTES (2 * STAGE_B)

template <int EPI, int HASB, int OSPL, int XWF>
__global__ void __launch_bounds__(256, 2) mmagemm_k(
    const bf16* __restrict__ Ah, const bf16* __restrict__ Al,
    const bf16* __restrict__ Bh, const bf16* __restrict__ Bl,
    float* __restrict__ C, bf16* __restrict__ Oh, bf16* __restrict__ Ol,
    const float* __restrict__ bias,
    int K, int ldc, long long sA, long long sB, long long sC)
{
    extern __shared__ __align__(16) char smem[];
    const int tid = threadIdx.x, lane = tid & 31, wid = tid >> 5;
    const int wm = (wid >> 2) * 64, wn = (wid & 3) * 32;
    const int bm = blockIdx.y << 7, bn = blockIdx.x << 7;
    Ah += blockIdx.z * sA;  Al += blockIdx.z * sA;
    Bh += blockIdx.z * sB;  Bl += blockIdx.z * sB;
    const uint32_t sbase = smem_u32(smem);
    const size_t rsk = (size_t)K * 2;

    float acc[4][4][4];
#pragma unroll
    for (int i = 0; i < 4; i++)
#pragma unroll
        for (int j = 0; j < 4; j++)
#pragma unroll
            for (int r = 0; r < 4; r++) acc[i][j][r] = 0.f;

    const char* pA0 = (const char*)Ah + (size_t)bm * rsk;
    const char* pA1 = (const char*)Al + (size_t)bm * rsk;
    const char* pB0 = (const char*)Bh + (size_t)bn * rsk;
    const char* pB1 = (const char*)Bl + (size_t)bn * rsk;

    // k0 in ELEMENTS (multiple of 32)
    auto issue = [&](int stage, int k0) {
        uint32_t d0 = sbase + stage * STAGE_B;
#pragma unroll
        for (int i = 0; i < 2; i++) {
            int task = tid + i * 256;
            int row = task >> 2, ch = task & 3;
            uint32_t doff = row * TSTRIDE + ch * 16;
            size_t goff = (size_t)row * rsk + (size_t)k0 * 2 + ch * 16;
            cpasync16(d0 + doff,              pA0 + goff);
            cpasync16(d0 + TILE_B + doff,     pA1 + goff);
            cpasync16(d0 + 2 * TILE_B + doff, pB0 + goff);
            cpasync16(d0 + 3 * TILE_B + doff, pB1 + goff);
        }
        asm volatile("cp.async.commit_group;" ::: "memory");
    };

    const int NK = K >> 5;
    issue(0, 0);
#pragma unroll 1
    for (int k = 0; k < NK; k++) {
        const int st = k & 1;
        if (k + 1 < NK) {
            issue(st ^ 1, (k + 1) << 5);
            asm volatile("cp.async.wait_group 1;" ::: "memory");
        } else {
            asm volatile("cp.async.wait_group 0;" ::: "memory");
        }
        __syncthreads();
        const uint32_t aB = sbase + st * STAGE_B;
        const int idx8 = lane & 7, q = lane >> 3;
#pragma unroll
        for (int ks = 0; ks < 2; ks++) {
            uint32_t arh[4][4], arl[4][4];
#pragma unroll
            for (int mf = 0; mf < 4; mf++) {
                uint32_t byte = (uint32_t)(wm + mf * 16 + (q & 1) * 8 + idx8) * TSTRIDE
                              + ks * 32 + (q >> 1) * 16;
                ldsm4(arh[mf], aB + byte);
                ldsm4(arl[mf], aB + TILE_B + byte);
            }
            uint32_t brh[4][2], brl[4][2];
#pragma unroll
            for (int nf2 = 0; nf2 < 2; nf2++) {
                uint32_t byte = (uint32_t)(wn + nf2 * 16 + (q >> 1) * 8 + idx8) * TSTRIDE
                              + ks * 32 + (q & 1) * 16;
                uint32_t r[4];
                ldsm4(r, aB + 2 * TILE_B + byte);
                brh[nf2 * 2][0] = r[0]; brh[nf2 * 2][1] = r[1];
                brh[nf2 * 2 + 1][0] = r[2]; brh[nf2 * 2 + 1][1] = r[3];
                ldsm4(r, aB + 3 * TILE_B + byte);
                brl[nf2 * 2][0] = r[0]; brl[nf2 * 2][1] = r[1];
                brl[nf2 * 2 + 1][0] = r[2]; brl[nf2 * 2 + 1][1] = r[3];
            }
#pragma unroll
            for (int mf = 0; mf < 4; mf++)
#pragma unroll
                for (int nf = 0; nf < 4; nf++) {
                    mma16816(acc[mf][nf], arh[mf], brh[nf]);
                    mma16816(acc[mf][nf], arh[mf], brl[nf]);
                    mma16816(acc[mf][nf], arl[mf], brh[nf]);
                }
        }
        __syncthreads();
    }

#pragma unroll
    for (int mf = 0; mf < 4; mf++) {
#pragma unroll
        for (int rh = 0; rh < 2; rh++) {
            int row = bm + wm + mf * 16 + (lane >> 2) + rh * 8;
#pragma unroll
            for (int nf = 0; nf < 4; nf++) {
                int col = bn + wn + nf * 8 + (lane & 3) * 2;
                float v0 = acc[mf][nf][rh * 2], v1 = acc[mf][nf][rh * 2 + 1];
                if (XWF) {
                    if (col < RH_) {
                        *(float2*)&C[(long long)row * RH_ + col] = make_float2(v0, v1);
                    } else {
                        int cc = col - RH_;
                        v0 += bias[cc]; v1 += bias[cc + 1];
                        *(float2*)&g_cat[(size_t)row * FF_ + HH_ + cc] = make_float2(v0, v1);
                    }
                    continue;
                }
                if (HASB) { v0 += bias[col]; v1 += bias[col + 1]; }
                if (EPI == 1) { v0 = fmaxf(v0, 0.f); v1 = fmaxf(v1, 0.f); }
                if (EPI == 2) { v0 = tanhf(v0); v1 = tanhf(v1); }
                long long idx = (long long)row * ldc + col + blockIdx.z * sC;
                if (OSPL) {
                    bf16 h0 = __float2bfloat16(v0), h1 = __float2bfloat16(v1);
                    __nv_bfloat162 hp, lp;
                    hp.x = h0; hp.y = h1;
                    lp.x = __float2bfloat16(v0 - __bfloat162float(h0));
                    lp.y = __float2bfloat16(v1 - __bfloat162float(h1));
                    *(__nv_bfloat162*)&Oh[idx] = hp;
                    *(__nv_bfloat162*)&Ol[idx] = lp;
                } else {
                    *(float2*)&C[idx] = make_float2(v0, v1);
                }
            }
        }
    }
}

// ---------------- counting + scatter ----------------
__global__ void zcnt_k() {
    int i = blockIdx.x * 256 + threadIdx.x;
    if (i < NBIN) g_cnt[i] = 0;
}
__global__ void zeroagg_k() {
    int i = blockIdx.x * 256 + threadIdx.x;
    if (i < NN_ * HH_) g_cat[(size_t)(i >> 8) * FF_ + (i & 255)] = 0.f;
}
__global__ void count_k(const int* __restrict__ ei, const int* __restrict__ et) {
    int e = blockIdx.x * 256 + threadIdx.x;
    if (e < EE_) atomicAdd(&g_cnt[ei[EE_ + e] * RR_ + et[e]], 1);
}
__global__ void scatter_msg_k(const int* __restrict__ ei, const int* __restrict__ et) {
    int e = blockIdx.x * 8 + (threadIdx.x >> 5);
    int lane = threadIdx.x & 31;
    if (e >= EE_) return;
    int s = ei[e], d = ei[EE_ + e], r = et[e];
    float inv = 1.0f / (float)max(g_cnt[d * RR_ + r], 1);
    const float4* p = (const float4*)(g_xw + (size_t)s * RH_ + r * HH_);
    float* o = g_cat + (size_t)d * FF_ + HH_;
#pragma unroll
    for (int i = 0; i < 2; ++i) {
        float4 v = p[lane + i * 32];
        v.x *= inv; v.y *= inv; v.z *= inv; v.w *= inv;
        red4(o + (lane + i * 32) * 4, v);
    }
}
__global__ void scatter_agg2_k(const int* __restrict__ ei) {
    int e = blockIdx.x * 8 + (threadIdx.x >> 5);
    int lane = threadIdx.x & 31;
    if (e >= EE_) return;
    int s = ei[e], d = ei[EE_ + e];
    const float4* p = (const float4*)(g_cat + (size_t)s * FF_ + HH_);
    float* o = g_cat + (size_t)d * FF_;
#pragma unroll
    for (int i = 0; i < 2; ++i) {
        float4 v = p[lane + i * 32];
        red4(o + (lane + i * 32) * 4, v);
    }
}

// ---------------- Wt = (comp x basis)^T ----------------
__global__ void __launch_bounds__(256) computeWt_k(
    const float* __restrict__ basis, const float* __restrict__ comp)
{
    __shared__ float cw[RR_ * NBASE_];
    __shared__ float T[32][33];
    int t = threadIdx.x;
    int f0 = blockIdx.x * 32, h0 = blockIdx.y * 32;
    for (int i = t; i < RR_ * NBASE_; i += 256) cw[i] = comp[i];
    __syncthreads();
    int hl = t & 31, fq = t >> 5;
    float acc[RR_][4];
#pragma unroll
    for (int r = 0; r < RR_; r++)
#pragma unroll
        for (int q = 0; q < 4; q++) acc[r][q] = 0.f;
#pragma unroll 1
    for (int b = 0; b < NBASE_; b++) {
        float bs[4];
#pragma unroll
        for (int q = 0; q < 4; q++)
            bs[q] = basis[((size_t)b * FF_ + f0 + fq * 4 + q) * HH_ + h0 + hl];
#pragma unroll
        for (int r = 0; r < RR_; r++) {
            float c = cw[r * NBASE_ + b];
#pragma unroll
            for (int q = 0; q < 4; q++) acc[r][q] = fmaf(c, bs[q], acc[r][q]);
        }
    }
#pragma unroll 1
    for (int r = 0; r < RR_; r++) {
        __syncthreads();
#pragma unroll
        for (int q = 0; q < 4; q++) T[hl][fq * 4 + q] = acc[r][q];
        __syncthreads();
        int row = t >> 3, c4 = (t & 7) * 4;
        float v0 = T[row][c4], v1 = T[row][c4 + 1], v2 = T[row][c4 + 2], v3 = T[row][c4 + 3];
        size_t o = (size_t)(r * HH_ + h0 + row) * FF_ + f0 + c4;
        bf16 b0 = __float2bfloat16(v0), b1 = __float2bfloat16(v1);
        bf16 b2 = __float2bfloat16(v2), b3 = __float2bfloat16(v3);
        __nv_bfloat162 hA, hB, lA, lB;
        hA.x = b0; hA.y = b1; hB.x = b2; hB.y = b3;
        lA.x = __float2bfloat16(v0 - __bfloat162float(b0));
        lA.y = __float2bfloat16(v1 - __bfloat162float(b1));
        lB.x = __float2bfloat16(v2 - __bfloat162float(b2));
        lB.y = __float2bfloat16(v3 - __bfloat162float(b3));
        *(__nv_bfloat162*)&g_wth[o] = hA; *(__nv_bfloat162*)&g_wth[o + 2] = hB;
        *(__nv_bfloat162*)&g_wtl[o] = lA; *(__nv_bfloat162*)&g_wtl[o + 2] = lB;
    }
}

// ---------------- misc prep ----------------
__global__ void split_k(const float* __restrict__ in, bf16* __restrict__ oh, bf16* __restrict__ ol, int n) {
    int i = blockIdx.x * 256 + threadIdx.x;
    if (i >= n) return;
    float v = in[i];
    bf16 h = __float2bfloat16(v);
    oh[i] = h;
    ol[i] = __float2bfloat16(v - __bfloat162float(h));
}
__global__ void tsplit_k(const float* __restrict__ in, bf16* __restrict__ oh, bf16* __restrict__ ol,
                         int ldi, int ldo) {
    __shared__ float t[32][33];
    int bx = blockIdx.x * 32, by = blockIdx.y * 32;
    int tx = threadIdx.x, ty = threadIdx.y;
#pragma unroll
    for (int j = 0; j < 4; ++j)
        t[ty + j * 8][tx] = in[(size_t)(by + ty + j * 8) * ldi + bx + tx];
    __syncthreads();
#pragma unroll
    for (int j = 0; j < 4; ++j) {
        float v = t[tx][ty + j * 8];
        size_t o = (size_t)(bx + ty + j * 8) * ldo + by + tx;
        bf16 h = __float2bfloat16(v);
        oh[o] = h;
        ol[o] = __float2bfloat16(v - __bfloat162float(h));
    }
}
__global__ void tspbf_k(const bf16* __restrict__ in, bf16* __restrict__ outT) {
    __shared__ bf16 t[32][33];
    const bf16* pin = in + (size_t)blockIdx.z * LL_ * DD_;
    bf16* pout = outT + (size_t)blockIdx.z * DD_ * LL_;
    int bx = blockIdx.x * 32, by = blockIdx.y * 32;
    int tx = threadIdx.x, ty = threadIdx.y;
#pragma unroll
    for (int j = 0; j < 4; ++j)
        t[ty + j * 8][tx] = pin[(size_t)(by + ty + j * 8) * DD_ + bx + tx];
    __syncthreads();
#pragma unroll
    for (int j = 0; j < 4; ++j)
        pout[(size_t)(bx + ty + j * 8) * LL_ + by + tx] = t[tx][ty + j * 8];
}
__global__ void xprep_k(const float* __restrict__ x) {
    int i = blockIdx.x * 256 + threadIdx.x;
    if (i >= NN_ * FF_) return;
    float v = x[i];
    bf16 h = __float2bfloat16(v);
    bf16 l = __float2bfloat16(v - __bfloat162float(h));
    g_xh[i] = h;
    g_xl[i] = l;
    size_t eo = (size_t)(i >> 9) * DD_ + (i & 511);
    g_emoh[eo] = h;
    g_emol[eo] = l;
}
__global__ void softmax_k() {
    const float* row = g_scores + (size_t)blockIdx.x * LL_;
    int t = threadIdx.x;
    int lane = t & 31, w = t >> 5;
    __shared__ float red[8];
    float v = row[t];
    float m = v;
#pragma unroll
    for (int o = 16; o > 0; o >>= 1) m = fmaxf(m, __shfl_xor_sync(0xffffffffu, m, o));
    if (lane == 0) red[w] = m;
    __syncthreads();
    m = red[0];
#pragma unroll
    for (int i = 1; i < 8; i++) m = fmaxf(m, red[i]);
    float e = expf(v - m);
    float s = e;
#pragma unroll
    for (int o = 16; o > 0; o >>= 1) s += __shfl_xor_sync(0xffffffffu, s, o);
    __syncthreads();
    if (lane == 0) red[w] = s;
    __syncthreads();
    s = 0.f;
#pragma unroll
    for (int i = 0; i < 8; i++) s += red[i];
    float a = e / s;
    bf16 hh = __float2bfloat16(a);
    size_t o = (size_t)blockIdx.x * LL_ + t;
    g_ah[o] = hh;
    g_al[o] = __float2bfloat16(a - __bfloat162float(hh));
}
__global__ void logits_k(const float* __restrict__ wfc, const float* __restrict__ bfc) {
    __shared__ float sw[HH_ * CC_];
    for (int i = threadIdx.x; i < HH_ * CC_; i += 256) sw[i] = wfc[i];
    __syncthreads();
    int n = blockIdx.x * 8 + (threadIdx.x >> 5);
    int lane = threadIdx.x & 31;
    const float* h = g_hidden + (size_t)n * HH_;
    float a[CC_];
#pragma unroll
    for (int c = 0; c < CC_; c++) a[c] = 0.f;
    for (int k = lane; k < HH_; k += 32) {
        float hv = h[k];
#pragma unroll
        for (int c = 0; c < CC_; c++) a[c] = fmaf(hv, sw[k * CC_ + c], a[c]);
    }
#pragma unroll
    for (int c = 0; c < CC_; c++)
#pragma unroll
        for (int o = 16; o > 0; o >>= 1) a[c] += __shfl_xor_sync(0xffffffffu, a[c], o);
    if (lane == 0)
#pragma unroll
        for (int c = 0; c < CC_; c++) g_logits[(size_t)n * CC_ + c] = a[c] + bfc[c];
}
__global__ void logsoftmax_k(float* __restrict__ out) {
    int u = blockIdx.x * 256 + threadIdx.x;
    if (u >= LL_ * CC_) return;
    int t = u / CC_, c = u % CC_;
    float vals[BB_];
    float m = -1e30f;
#pragma unroll
    for (int b = 0; b < BB_; b++) {
        vals[b] = g_logits[((size_t)(b * LL_ + t)) * CC_ + c];
        m = fmaxf(m, vals[b]);
    }
    float s = 0.f;
#pragma unroll
    for (int b = 0; b < BB_; b++) s += expf(vals[b] - m);
    float lse = m + logf(s);
#pragma unroll
    for (int b = 0; b < BB_; b++) out[((size_t)t * BB_ + b) * CC_ + c] = vals[b] - lse;
}

// ---------------- host ----------------
extern "C" void kernel_launch(void* const* d_in, const int* in_sizes, int n_in,
                              void* d_out, int out_size)
{
    const float* x      = (const float*)d_in[0];
    const int*   ei     = (const int*)  d_in[1];
    const int*   et     = (const int*)  d_in[3];
    const float* basis  = (const float*)d_in[8];
    const float* comp   = (const float*)d_in[9];
    const float* root1  = (const float*)d_in[10];
    const float* bias1  = (const float*)d_in[11];
    const float* w_rel  = (const float*)d_in[12];
    const float* b_rel  = (const float*)d_in[13];
    const float* w_root = (const float*)d_in[14];
    const float* w_att  = (const float*)d_in[15];
    const float* b_att  = (const float*)d_in[16];
    const float* w_lin  = (const float*)d_in[17];
    const float* b_lin  = (const float*)d_in[18];
    const float* w_fc   = (const float*)d_in[19];
    const float* b_fc   = (const float*)d_in[20];
    float* out = (float*)d_out;

    float *pxw, *pcat, *pscores, *phid;
    bf16 *pxh, *pxl, *pwth, *pwtl, *pw2h, *pw2l, *pwah, *pwal,
         *pwlh, *pwll, *pch, *pcl, *peh, *pel, *pXh, *pXl, *pah, *pal,
         *peTh, *peTl, *path, *patl;
    cudaGetSymbolAddress((void**)&pxw, g_xw);
    cudaGetSymbolAddress((void**)&pcat, g_cat);
    cudaGetSymbolAddress((void**)&pscores, g_scores);
    cudaGetSymbolAddress((void**)&phid, g_hidden);
    cudaGetSymbolAddress((void**)&pxh, g_xh);   cudaGetSymbolAddress((void**)&pxl, g_xl);
    cudaGetSymbolAddress((void**)&pwth, g_wth); cudaGetSymbolAddress((void**)&pwtl, g_wtl);
    cudaGetSymbolAddress((void**)&pw2h, g_w2th); cudaGetSymbolAddress((void**)&pw2l, g_w2tl);
    cudaGetSymbolAddress((void**)&pwah, g_wath); cudaGetSymbolAddress((void**)&pwal, g_watl);
    cudaGetSymbolAddress((void**)&pwlh, g_wlth); cudaGetSymbolAddress((void**)&pwll, g_wltl);
    cudaGetSymbolAddress((void**)&pch, g_cath);  cudaGetSymbolAddress((void**)&pcl, g_catl);
    cudaGetSymbolAddress((void**)&peh, g_emoh);  cudaGetSymbolAddress((void**)&pel, g_emol);
    cudaGetSymbolAddress((void**)&pXh, g_Xh);    cudaGetSymbolAddress((void**)&pXl, g_Xl);
    cudaGetSymbolAddress((void**)&pah, g_ah);    cudaGetSymbolAddress((void**)&pal, g_al);
    cudaGetSymbolAddress((void**)&peTh, g_eTh);  cudaGetSymbolAddress((void**)&peTl, g_eTl);
    cudaGetSymbolAddress((void**)&path, g_atth); cudaGetSymbolAddress((void**)&patl, g_attl);

    cudaFuncSetAttribute(mmagemm_k<0,0,0,1>, cudaFuncAttributeMaxDynamicSharedMemorySize, SMEM_BYTES);
    cudaFuncSetAttribute(mmagemm_k<0,1,1,0>, cudaFuncAttributeMaxDynamicSharedMemorySize, SMEM_BYTES);
    cudaFuncSetAttribute(mmagemm_k<2,0,0,0>, cudaFuncAttributeMaxDynamicSharedMemorySize, SMEM_BYTES);
    cudaFuncSetAttribute(mmagemm_k<0,0,1,0>, cudaFuncAttributeMaxDynamicSharedMemorySize, SMEM_BYTES);
    cudaFuncSetAttribute(mmagemm_k<1,1,0,0>, cudaFuncAttributeMaxDynamicSharedMemorySize, SMEM_BYTES);

    // prep (serial, default stream)
    zcnt_k<<<NBIN / 256, 256>>>();
    zeroagg_k<<<(NN_ * HH_ + 255) / 256, 256>>>();
    count_k<<<EE_ / 256, 256>>>(ei, et);
    computeWt_k<<<dim3(FF_ / 32, HH_ / 32), 256>>>(basis, comp);
    xprep_k<<<NN_ * FF_ / 256, 256>>>(x);
    // root1^T appended to Wcat^T rows [4096:4352)
    tsplit_k<<<dim3(8, 16), dim3(32, 8)>>>(root1, pwth + (size_t)RH_ * FF_, pwtl + (size_t)RH_ * FF_, HH_, FF_);
    tsplit_k<<<dim3(8, 8),  dim3(32, 8)>>>(w_rel,  pw2h, pw2l, HH_, FF_);
    tsplit_k<<<dim3(8, 8),  dim3(32, 8)>>>(w_root, pw2h + HH_, pw2l + HH_, HH_, FF_);
    tsplit_k<<<dim3(24, 24), dim3(32, 8)>>>(w_att, pwah, pwal, DD_, DD_);
    tsplit_k<<<dim3(8, 24),  dim3(32, 8)>>>(w_lin, pwlh, pwll, HH_, DD_);

    // fused: xw = x @ Wcat  AND  out1 base = x @ root1 + bias1
    mmagemm_k<0,0,0,1><<<dim3(NW_ / 128, 64), 256, SMEM_BYTES>>>(
        pxh, pxl, pwth, pwtl, pxw, nullptr, nullptr, bias1, FF_, RH_, 0, 0, 0);
    // atomic scatters
    scatter_msg_k<<<EE_ / 8, 256>>>(ei, et);
    scatter_agg2_k<<<EE_ / 8, 256>>>(ei);
    // split cat; out2 = [agg2|out1] @ [w_rel;w_root] + b_rel -> emotions[:,512:768] (bf16 split)
    split_k<<<NN_ * FF_ / 256, 256>>>(pcat, pch, pcl, NN_ * FF_);
    mmagemm_k<0,1,1,0><<<dim3(2, 64), 256, SMEM_BYTES>>>(
        pch, pcl, pw2h, pw2l, nullptr, peh + FF_, pel + FF_, b_rel, FF_, DD_, 0, 0, 0);
    // X = emotions @ w_att + b_att (bf16 split out)
    mmagemm_k<0,1,1,0><<<dim3(6, 64), 256, SMEM_BYTES>>>(
        peh, pel, pwah, pwal, nullptr, pXh, pXl, b_att, DD_, DD_, 0, 0, 0);
    // scores = tanh(X_b @ emotions_b^T)
    mmagemm_k<2,0,0,0><<<dim3(2, 2, BB_), 256, SMEM_BYTES>>>(
        pXh, pXl, peh, pel, pscores, nullptr, nullptr, nullptr, DD_, LL_,
        (long long)LL_ * DD_, (long long)LL_ * DD_, (long long)LL_ * LL_);
    softmax_k<<<BB_ * LL_, LL_>>>();
    // emotions^T per batch (bf16)
    tspbf_k<<<dim3(24, 8, BB_), dim3(32, 8)>>>(peh, peTh);
    tspbf_k<<<dim3(24, 8, BB_), dim3(32, 8)>>>(pel, peTl);
    // att = a_b @ emotions_b (bf16 split out)
    mmagemm_k<0,0,1,0><<<dim3(6, 2, BB_), 256, SMEM_BYTES>>>(
        pah, pal, peTh, peTl, nullptr, path, patl, nullptr, LL_, DD_,
        (long long)LL_ * LL_, (long long)DD_ * LL_, (long long)LL_ * DD_);
    // hidden = relu(att @ w_lin + b_lin)
    mmagemm_k<1,1,0,0><<<dim3(2, 64), 256, SMEM_BYTES>>>(
        path, patl, pwlh, pwll, phid, nullptr, nullptr, b_lin, DD_, HH_, 0, 0, 0);
    // logits + log_softmax
    logits_k<<<NN_ / 8, 256>>>(w_fc, b_fc);
    logsoftmax_k<<<(LL_ * CC_ + 255) / 256, 256>>>(out);
}